// round 15
// baseline (speedup 1.0000x reference)
#include <cuda_runtime.h>
#include <cstdint>
#include <math.h>

// Problem dims
#define B_   64
#define T_   512
#define NU_  256
#define NX_  1024

// Recurrence config: 128 blocks, block owns all 64 rows x 8 cols.
// 256 threads = 2 K-groups (khalf) x 128 slots. Slot s: row = s>>1, ui = s&1 (4 cols).
#define GBLKS    128
#define CPB      8
#define RTHREADS 256
#define KC       64
#define NBUF     6
#define XLD      68          // padded chunk row stride (272B, 16B-aligned, 8B-aligned rows)
#define BUFF     (B_ * XLD)  // 4352 floats per buffer

// Phase-1 GEMM config
#define BM 64
#define BN 64
#define BK 16

typedef unsigned long long u64;

// ---------------- device scratch ----------------
__device__ float d_az[(size_t)B_ * T_ * NX_];
__device__ float d_af[(size_t)B_ * T_ * NX_];
__device__ float d_ar[(size_t)B_ * T_ * NX_];
__device__ float d_xA[B_ * NX_];
__device__ float d_xB[B_ * NX_];
__device__ float d_g[B_ * NX_];
__device__ unsigned d_barc[8 * 32];   // 8 counters, 128B apart

// ---------------- packed f32x2 helpers (sm_103a) ----------------
__device__ __forceinline__ u64 pack2(float x, float y) {
    u64 r; asm("mov.b64 %0, {%1,%2};" : "=l"(r) : "f"(x), "f"(y)); return r;
}
__device__ __forceinline__ void ffma2(u64& d, u64 a, u64 b) {
    asm("fma.rn.f32x2 %0, %1, %2, %0;" : "+l"(d) : "l"(a), "l"(b));
}
__device__ __forceinline__ u64 fadd2(u64 a, u64 b) {
    u64 r; asm("add.rn.f32x2 %0, %1, %2;" : "=l"(r) : "l"(a), "l"(b)); return r;
}
__device__ __forceinline__ void unpack2(u64 v, float& x, float& y) {
    asm("mov.b64 {%0,%1}, %2;" : "=f"(x), "=f"(y) : "l"(v));
}
__device__ __forceinline__ float hadd2(u64 v) {
    float x, y; unpack2(v, x, y); return x + y;
}

// ---------------- cp.async helpers ----------------
__device__ __forceinline__ void cp_async16(void* smem_dst, const void* gmem_src) {
    uint32_t saddr = (uint32_t)__cvta_generic_to_shared(smem_dst);
    asm volatile("cp.async.cg.shared.global [%0], [%1], 16;\n" :: "r"(saddr), "l"(gmem_src));
}
__device__ __forceinline__ void cp_commit() { asm volatile("cp.async.commit_group;\n"); }
template <int N>
__device__ __forceinline__ void cp_wait() { asm volatile("cp.async.wait_group %0;\n" :: "n"(N)); }

// Load chunk pair (2*pair, 2*pair+1) of src [64][NX_] into ring buffers. One commit group.
__device__ __forceinline__ void load_pair(float* bufs, const float* src, int pair, int tid) {
#pragma unroll
    for (int h = 0; h < 2; ++h) {
        const int c = 2 * pair + h;
        float* dst = bufs + (c % NBUF) * BUFF;
        const int cb = c * KC;
#pragma unroll
        for (int q = 0; q < 4; ++q) {
            const int idx = tid + q * RTHREADS;   // 0..1023
            const int row = idx >> 4;             // 16 float4 per row
            const int c4  = idx & 15;
            cp_async16(dst + row * XLD + c4 * 4, src + (size_t)row * NX_ + cb + c4 * 4);
        }
    }
    cp_commit();
}

// ---------------- grid-wide monotone barrier: 8 split counters ----------------
// Arrival: 1 release-add to counter (bid&7). Wait: lanes 0..7 each poll one counter,
// warp-collective sum via shfl; exit when sum >= target. Counters reset by init_kernel.
__device__ __forceinline__ void grid_barrier(unsigned target) {
    __syncthreads();
    const int tid = threadIdx.x;
    if (tid == 0) {
        asm volatile("red.release.gpu.global.add.u32 [%0], %1;"
                     :: "l"(&d_barc[(blockIdx.x & 7) * 32]), "r"(1u) : "memory");
    }
    if (tid < 8) {
        int spins = 0;
        while (true) {
            unsigned v;
            asm volatile("ld.acquire.gpu.global.u32 %0, [%1];"
                         : "=r"(v) : "l"(&d_barc[tid * 32]) : "memory");
            unsigned sum = v;
            sum += __shfl_xor_sync(0xFFu, sum, 4, 8);
            sum += __shfl_xor_sync(0xFFu, sum, 2, 8);
            sum += __shfl_xor_sync(0xFFu, sum, 1, 8);
            if (sum >= target) break;
            if (++spins > 2) __nanosleep(50);
        }
    }
    __syncthreads();
}

// ---------------- init: reset counters + copy x0 into state buffer ----------------
__global__ void init_kernel(const float* __restrict__ x0) {
    if (blockIdx.x == 0 && threadIdx.x < 8 * 32) d_barc[threadIdx.x] = 0;
    const int i = blockIdx.x * blockDim.x + threadIdx.x;
    float4 v = *(const float4*)&x0[i * 4];
    *(float4*)&d_xA[i * 4] = v;
}

// ---------------- Phase 1: a{z,f,r} = u @ W + b (k-paired FFMA2) ----------------
__global__ void __launch_bounds__(256) inproj_kernel(
    const float* __restrict__ u,
    const float* __restrict__ Wz, const float* __restrict__ Wf, const float* __restrict__ Wr,
    const float* __restrict__ bz, const float* __restrict__ bf, const float* __restrict__ br)
{
    __shared__ float As[BM][BK + 2];      // stride 18 floats = 72B (8B-aligned u64 reads)
    __shared__ u64   Bs2[BK / 2][BN];     // k-pair interleaved: Bs2[k2][n] = {W[2k2,n], W[2k2+1,n]}

    const int gate = blockIdx.z;
    const float* W    = (gate == 0) ? Wz : (gate == 1) ? Wf : Wr;
    const float* bias = (gate == 0) ? bz : (gate == 1) ? bf : br;
    float* out        = (gate == 0) ? d_az : (gate == 1) ? d_af : d_ar;

    const int m0 = blockIdx.y * BM;
    const int n0 = blockIdx.x * BN;
    const int tid = threadIdx.x;
    const int tx = tid % 16;
    const int ty = tid / 16;

    u64 aC0[4], aC1[4], aC2[4], aC3[4];   // k-paired accs: 4 rows x 4 cols
#pragma unroll
    for (int i = 0; i < 4; i++) { aC0[i] = 0; aC1[i] = 0; aC2[i] = 0; aC3[i] = 0; }

    for (int k0 = 0; k0 < NU_; k0 += BK) {
        {
            const int r = tid >> 2, q = tid & 3;
            float4 v = *(const float4*)&u[(size_t)(m0 + r) * NU_ + k0 + q * 4];
            As[r][q * 4 + 0] = v.x; As[r][q * 4 + 1] = v.y;
            As[r][q * 4 + 2] = v.z; As[r][q * 4 + 3] = v.w;
        }
        {
            const int k2 = tid >> 5, cg = tid & 31;    // cols 2cg, 2cg+1
            const float2 w0 = *(const float2*)&W[(size_t)(k0 + 2 * k2) * NX_ + n0 + cg * 2];
            const float2 w1 = *(const float2*)&W[(size_t)(k0 + 2 * k2 + 1) * NX_ + n0 + cg * 2];
            Bs2[k2][cg * 2 + 0] = pack2(w0.x, w1.x);
            Bs2[k2][cg * 2 + 1] = pack2(w0.y, w1.y);
        }
        __syncthreads();
#pragma unroll
        for (int k2 = 0; k2 < BK / 2; ++k2) {
            const ulonglong2* bp = (const ulonglong2*)&Bs2[k2][tx * 4];
            const ulonglong2 b01 = bp[0];
            const ulonglong2 b23 = bp[1];
#pragma unroll
            for (int i = 0; i < 4; i++) {
                const u64 a = *(const u64*)&As[ty * 4 + i][k2 * 2];
                ffma2(aC0[i], a, b01.x);
                ffma2(aC1[i], a, b01.y);
                ffma2(aC2[i], a, b23.x);
                ffma2(aC3[i], a, b23.y);
            }
        }
        __syncthreads();
    }

    const float b0 = __ldg(&bias[n0 + tx * 4 + 0]);
    const float b1 = __ldg(&bias[n0 + tx * 4 + 1]);
    const float b2 = __ldg(&bias[n0 + tx * 4 + 2]);
    const float b3 = __ldg(&bias[n0 + tx * 4 + 3]);
#pragma unroll
    for (int i = 0; i < 4; i++) {
        float4 o = make_float4(hadd2(aC0[i]) + b0, hadd2(aC1[i]) + b1,
                               hadd2(aC2[i]) + b2, hadd2(aC3[i]) + b3);
        *(float4*)&out[(size_t)(m0 + ty * 4 + i) * NX_ + n0 + tx * 4] = o;
    }
}

// ---------------- Phase 2: persistent recurrence (k-paired FFMA2, split-K) ----------------
// Smem U layouts (k-pair interleaved):
//  Uzp floats: [k2][col][4] = {Uz[2k2,c], Uz[2k2+1,c], Uf[2k2,c], Uf[2k2+1,c]}  (16384 f)
//  Urp floats: [k2][col][2] = {Ur[2k2,c], Ur[2k2+1,c]}                           (8192 f)
extern __shared__ float recur_smem[];

__global__ void __launch_bounds__(RTHREADS, 1) recur_kernel(
    const float* __restrict__ Uz, const float* __restrict__ Uf, const float* __restrict__ Ur,
    float* __restrict__ out)
{
    float* Uzp  = recur_smem;                  // 16384 f
    float* Urp  = Uzp + NX_ * 16;              // 8192 f
    float* bufs = Urp + NX_ * 8;               // 6 * 4352 f
    u64*   scr  = (u64*)(bufs + NBUF * BUFF);  // 128 slots * 8 u64 = 8KB

    const int tid = threadIdx.x;
    const int bid = blockIdx.x;
    const int j0 = bid * CPB;

    const int s     = tid & 127;
    const int khalf = tid >> 7;                // 0: even chunks, 1: odd chunks
    const int row   = s >> 1;
    const int ui    = s & 1;
    const int jb    = j0 + ui * 4;

    // Stage U slices, k-pair interleaved (one-time)
    for (int i = tid; i < (NX_ / 2) * CPB; i += RTHREADS) {
        const int k2 = i >> 3, col = i & 7;
        const float* pz = &Uz[(size_t)(2 * k2) * NX_ + j0 + col];
        const float* pf = &Uf[(size_t)(2 * k2) * NX_ + j0 + col];
        const float* pr = &Ur[(size_t)(2 * k2) * NX_ + j0 + col];
        float* uz = &Uzp[k2 * 32 + col * 4];
        uz[0] = pz[0]; uz[1] = pz[NX_];
        uz[2] = pf[0]; uz[3] = pf[NX_];
        float* ur = &Urp[k2 * 16 + col * 2];
        ur[0] = pr[0]; ur[1] = pr[NX_];
    }
    __syncthreads();

    // Thread views: per k2, UzT[k2*8 + c] = {z-pair, f-pair} for col jb+c (c=0..3);
    //               UrT[k2*4 + c] = {r-pair col jb+2c, r-pair col jb+2c+1}.
    const ulonglong2* UzT = (const ulonglong2*)Uzp + ui * 4;
    const ulonglong2* UrT = (const ulonglong2*)Urp + ui * 2;

    float* xcur  = d_xA;
    float* xnext = d_xB;
    unsigned target = GBLKS;

    float zv[4];     // z gate values (khalf==0 threads)
    float4 xc;       // this thread's own 4 state cols, carried in registers
    if (khalf == 0) xc = *(const float4*)&d_xA[(size_t)row * NX_ + jb];

    for (int t = 0; t < T_; ++t) {
        // ================= ZF phase: z = sig(az + x@Uz), f = sig(af + x@Uf) ============
        u64 az0 = 0, az1 = 0, az2 = 0, az3 = 0;
        u64 af0 = 0, af1 = 0, af2 = 0, af3 = 0;
        float4 az4, af4;
        if (khalf == 0) {
            const size_t aoff = ((size_t)row * T_ + t) * NX_ + jb;
            az4 = __ldcs((const float4*)&d_az[aoff]);
            af4 = __ldcs((const float4*)&d_af[aoff]);
            // io_delay: output at step t is the PRE-update state (in registers)
            __stcs((float4*)&out[aoff], xc);
        }

        load_pair(bufs, xcur, 0, tid);
        load_pair(bufs, xcur, 1, tid);
        load_pair(bufs, xcur, 2, tid);
#pragma unroll 1
        for (int p = 0; p < 8; ++p) {
            if (p < 6) cp_wait<2>(); else if (p == 6) cp_wait<1>(); else cp_wait<0>();
            __syncthreads();
            const int c = 2 * p + khalf;
            const u64* xb = (const u64*)(bufs + (c % NBUF) * BUFF + row * XLD);
            const int k2b = c * (KC / 2);
#pragma unroll 8
            for (int kk2 = 0; kk2 < KC / 2; ++kk2) {
                const u64 xp = xb[kk2];
                const ulonglong2* Up = UzT + (size_t)(k2b + kk2) * 8;
                const ulonglong2 U0 = Up[0], U1 = Up[1];
                ffma2(az0, xp, U0.x); ffma2(af0, xp, U0.y);
                ffma2(az1, xp, U1.x); ffma2(af1, xp, U1.y);
                const ulonglong2 U2 = Up[2], U3 = Up[3];
                ffma2(az2, xp, U2.x); ffma2(af2, xp, U2.y);
                ffma2(az3, xp, U3.x); ffma2(af3, xp, U3.y);
            }
            __syncthreads();
            if (p < 5) load_pair(bufs, xcur, p + 3, tid);
        }
        // cross-half reduction
        if (khalf == 1) {
            ulonglong2* dst = (ulonglong2*)(scr + (size_t)s * 8);
            dst[0] = make_ulonglong2(az0, az1);
            dst[1] = make_ulonglong2(az2, az3);
            dst[2] = make_ulonglong2(af0, af1);
            dst[3] = make_ulonglong2(af2, af3);
        }
        __syncthreads();
        if (khalf == 0) {
            const ulonglong2* sp = (const ulonglong2*)(scr + (size_t)s * 8);
            const ulonglong2 oa = sp[0], ob = sp[1], oc = sp[2], od = sp[3];
            az0 = fadd2(az0, oa.x); az1 = fadd2(az1, oa.y);
            az2 = fadd2(az2, ob.x); az3 = fadd2(az3, ob.y);
            af0 = fadd2(af0, oc.x); af1 = fadd2(af1, oc.y);
            af2 = fadd2(af2, od.x); af3 = fadd2(af3, od.y);

            const float zp0 = hadd2(az0) + az4.x, zp1 = hadd2(az1) + az4.y;
            const float zp2 = hadd2(az2) + az4.z, zp3 = hadd2(az3) + az4.w;
            const float fp0 = hadd2(af0) + af4.x, fp1 = hadd2(af1) + af4.y;
            const float fp2 = hadd2(af2) + af4.z, fp3 = hadd2(af3) + af4.w;

            zv[0] = 1.0f / (1.0f + __expf(-zp0));
            zv[1] = 1.0f / (1.0f + __expf(-zp1));
            zv[2] = 1.0f / (1.0f + __expf(-zp2));
            zv[3] = 1.0f / (1.0f + __expf(-zp3));
            float4 g4;
            g4.x = xc.x / (1.0f + __expf(-fp0));
            g4.y = xc.y / (1.0f + __expf(-fp1));
            g4.z = xc.z / (1.0f + __expf(-fp2));
            g4.w = xc.w / (1.0f + __expf(-fp3));
            __stcg((float4*)&d_g[(size_t)row * NX_ + jb], g4);
        }
        grid_barrier(target); target += GBLKS;

        // ================= R phase: r = tanh(ar + g@Ur); x_next = z*x + (1-z)*r ========
        u64 ar0 = 0, ar1 = 0, ar2 = 0, ar3 = 0;
        float4 ar4;
        if (khalf == 0)
            ar4 = __ldcs((const float4*)&d_ar[((size_t)row * T_ + t) * NX_ + jb]);

        load_pair(bufs, d_g, 0, tid);
        load_pair(bufs, d_g, 1, tid);
        load_pair(bufs, d_g, 2, tid);
#pragma unroll 1
        for (int p = 0; p < 8; ++p) {
            if (p < 6) cp_wait<2>(); else if (p == 6) cp_wait<1>(); else cp_wait<0>();
            __syncthreads();
            const int c = 2 * p + khalf;
            const u64* gb = (const u64*)(bufs + (c % NBUF) * BUFF + row * XLD);
            const int k2b = c * (KC / 2);
#pragma unroll 8
            for (int kk2 = 0; kk2 < KC / 2; ++kk2) {
                const u64 gp = gb[kk2];
                const ulonglong2* Up = UrT + (size_t)(k2b + kk2) * 4;
                const ulonglong2 V0 = Up[0];
                ffma2(ar0, gp, V0.x); ffma2(ar1, gp, V0.y);
                const ulonglong2 V1 = Up[1];
                ffma2(ar2, gp, V1.x); ffma2(ar3, gp, V1.y);
            }
            __syncthreads();
            if (p < 5) load_pair(bufs, d_g, p + 3, tid);
        }
        if (khalf == 1) {
            ulonglong2* dst = (ulonglong2*)(scr + (size_t)s * 8);
            dst[0] = make_ulonglong2(ar0, ar1);
            dst[1] = make_ulonglong2(ar2, ar3);
        }
        __syncthreads();
        if (khalf == 0) {
            const ulonglong2* sp = (const ulonglong2*)(scr + (size_t)s * 8);
            const ulonglong2 oa = sp[0], ob = sp[1];
            ar0 = fadd2(ar0, oa.x); ar1 = fadd2(ar1, oa.y);
            ar2 = fadd2(ar2, ob.x); ar3 = fadd2(ar3, ob.y);

            const float rp0 = hadd2(ar0) + ar4.x, rp1 = hadd2(ar1) + ar4.y;
            const float rp2 = hadd2(ar2) + ar4.z, rp3 = hadd2(ar3) + ar4.w;
            float4 xn;
            xn.x = zv[0] * xc.x + (1.0f - zv[0]) * tanhf(rp0);
            xn.y = zv[1] * xc.y + (1.0f - zv[1]) * tanhf(rp1);
            xn.z = zv[2] * xc.z + (1.0f - zv[2]) * tanhf(rp2);
            xn.w = zv[3] * xc.w + (1.0f - zv[3]) * tanhf(rp3);
            __stcg((float4*)&xnext[(size_t)row * NX_ + jb], xn);
            xc = xn;   // carry own state in registers
        }
        grid_barrier(target); target += GBLKS;

        float* tmp = xcur; xcur = xnext; xnext = tmp;
    }
}

// ---------------- launch ----------------
extern "C" void kernel_launch(void* const* d_in, const int* in_sizes, int n_in,
                              void* d_out, int out_size) {
    const float* u  = (const float*)d_in[0];
    const float* x0 = (const float*)d_in[1];
    const float* Wz = (const float*)d_in[2];
    const float* Uz = (const float*)d_in[3];
    const float* bz = (const float*)d_in[4];
    const float* Wf = (const float*)d_in[5];
    const float* Uf = (const float*)d_in[6];
    const float* bf = (const float*)d_in[7];
    const float* Wr = (const float*)d_in[8];
    const float* Ur = (const float*)d_in[9];
    const float* br = (const float*)d_in[10];
    float* out = (float*)d_out;

    init_kernel<<<64, 256>>>(x0);

    dim3 g1(NX_ / BN, (B_ * T_) / BM, 3);
    inproj_kernel<<<g1, 256>>>(u, Wz, Wf, Wr, bz, bf, br);

    // smem: Uzp 16384 + Urp 8192 + bufs 26112 + scr 2048 floats = 210,944 B
    const int smem_bytes = (NX_ * 16 + NX_ * 8 + NBUF * BUFF + 2048) * (int)sizeof(float);
    cudaFuncSetAttribute(recur_kernel, cudaFuncAttributeMaxDynamicSharedMemorySize, smem_bytes);
    recur_kernel<<<GBLKS, RTHREADS, smem_bytes>>>(Uz, Uf, Ur, out);
}

// round 17
// speedup vs baseline: 1.1179x; 1.1179x over previous
#include <cuda_runtime.h>
#include <cstdint>
#include <math.h>

// Problem dims
#define B_   64
#define T_   512
#define NU_  256
#define NX_  1024

// Recurrence config: 128 blocks, block owns all 64 rows x 8 cols.
// 256 threads = 2 K-groups (khalf) x 128 slots. Slot s: row = s>>1, ui = s&1 (4 cols).
// Warp w: rows 16*(w&3)..+15, khalf = w>>2. Warp-private chunk ring, NO block syncs in mainloop.
#define GBLKS    128
#define CPB      8
#define RTHREADS 256
#define KC       64
#define WNBUF    3            // per-warp ring slots
#define XLD      68           // padded chunk row stride (272B, 8B/16B-aligned)
#define WROWS    16
#define WBUFF    (WROWS * XLD)        // 1088 floats per slot
#define WREGION  (WNBUF * WBUFF)      // 3264 floats per warp

// Phase-1 GEMM config
#define BM 64
#define BN 64
#define BK 16

typedef unsigned long long u64;

// ---------------- device scratch ----------------
__device__ float d_az[(size_t)B_ * T_ * NX_];
__device__ float d_af[(size_t)B_ * T_ * NX_];
__device__ float d_ar[(size_t)B_ * T_ * NX_];
__device__ float d_xA[B_ * NX_];
__device__ float d_xB[B_ * NX_];
__device__ float d_g[B_ * NX_];
__device__ unsigned d_barc[8 * 32];   // 8 counters, 128B apart

// ---------------- packed f32x2 helpers (sm_103a) ----------------
__device__ __forceinline__ u64 pack2(float x, float y) {
    u64 r; asm("mov.b64 %0, {%1,%2};" : "=l"(r) : "f"(x), "f"(y)); return r;
}
__device__ __forceinline__ void ffma2(u64& d, u64 a, u64 b) {
    asm("fma.rn.f32x2 %0, %1, %2, %0;" : "+l"(d) : "l"(a), "l"(b));
}
__device__ __forceinline__ u64 fadd2(u64 a, u64 b) {
    u64 r; asm("add.rn.f32x2 %0, %1, %2;" : "=l"(r) : "l"(a), "l"(b)); return r;
}
__device__ __forceinline__ void unpack2(u64 v, float& x, float& y) {
    asm("mov.b64 {%0,%1}, %2;" : "=f"(x), "=f"(y) : "l"(v));
}
__device__ __forceinline__ float hadd2(u64 v) {
    float x, y; unpack2(v, x, y); return x + y;
}

// ---------------- cp.async helpers ----------------
__device__ __forceinline__ void cp_async16(void* smem_dst, const void* gmem_src) {
    uint32_t saddr = (uint32_t)__cvta_generic_to_shared(smem_dst);
    asm volatile("cp.async.cg.shared.global [%0], [%1], 16;\n" :: "r"(saddr), "l"(gmem_src));
}
__device__ __forceinline__ void cp_commit() { asm volatile("cp.async.commit_group;\n"); }
template <int N>
__device__ __forceinline__ void cp_wait() { asm volatile("cp.async.wait_group %0;\n" :: "n"(N)); }

// Warp-private: load 16 rows (r0..r0+15) of chunk c into ring slot. One commit group.
// 16 rows x 16 float4 = 256 transfers; 8 per lane.
__device__ __forceinline__ void load_chunk_w(float* wbuf, const float* src, int r0, int slot,
                                             int c, int lane) {
    float* dst = wbuf + slot * WBUFF;
    const int cb = c * KC;
#pragma unroll
    for (int q = 0; q < 8; ++q) {
        const int idx = lane + q * 32;        // 0..255
        const int rl  = idx >> 4;             // 0..15
        const int c4  = idx & 15;
        cp_async16(dst + rl * XLD + c4 * 4, src + (size_t)(r0 + rl) * NX_ + cb + c4 * 4);
    }
    cp_commit();
}

// ---------------- grid-wide monotone barrier: 8 split counters ----------------
__device__ __forceinline__ void grid_barrier(unsigned target) {
    __syncthreads();
    const int tid = threadIdx.x;
    if (tid == 0) {
        asm volatile("red.release.gpu.global.add.u32 [%0], %1;"
                     :: "l"(&d_barc[(blockIdx.x & 7) * 32]), "r"(1u) : "memory");
    }
    if (tid < 8) {
        int spins = 0;
        while (true) {
            unsigned v;
            asm volatile("ld.acquire.gpu.global.u32 %0, [%1];"
                         : "=r"(v) : "l"(&d_barc[tid * 32]) : "memory");
            unsigned sum = v;
            sum += __shfl_xor_sync(0xFFu, sum, 4, 8);
            sum += __shfl_xor_sync(0xFFu, sum, 2, 8);
            sum += __shfl_xor_sync(0xFFu, sum, 1, 8);
            if (sum >= target) break;
            if (++spins > 2) __nanosleep(50);
        }
    }
    __syncthreads();
}

// ---------------- init: reset counters + copy x0 into state buffer ----------------
__global__ void init_kernel(const float* __restrict__ x0) {
    if (blockIdx.x == 0 && threadIdx.x < 8 * 32) d_barc[threadIdx.x] = 0;
    const int i = blockIdx.x * blockDim.x + threadIdx.x;
    float4 v = *(const float4*)&x0[i * 4];
    *(float4*)&d_xA[i * 4] = v;
}

// ---------------- Phase 1: a{z,f,r} = u @ W + b (k-paired FFMA2) ----------------
__global__ void __launch_bounds__(256) inproj_kernel(
    const float* __restrict__ u,
    const float* __restrict__ Wz, const float* __restrict__ Wf, const float* __restrict__ Wr,
    const float* __restrict__ bz, const float* __restrict__ bf, const float* __restrict__ br)
{
    __shared__ float As[BM][BK + 2];      // stride 18 floats (8B-aligned u64 reads)
    __shared__ u64   Bs2[BK / 2][BN];     // k-pair interleaved

    const int gate = blockIdx.z;
    const float* W    = (gate == 0) ? Wz : (gate == 1) ? Wf : Wr;
    const float* bias = (gate == 0) ? bz : (gate == 1) ? bf : br;
    float* out        = (gate == 0) ? d_az : (gate == 1) ? d_af : d_ar;

    const int m0 = blockIdx.y * BM;
    const int n0 = blockIdx.x * BN;
    const int tid = threadIdx.x;
    const int tx = tid % 16;
    const int ty = tid / 16;

    u64 aC0[4], aC1[4], aC2[4], aC3[4];
#pragma unroll
    for (int i = 0; i < 4; i++) { aC0[i] = 0; aC1[i] = 0; aC2[i] = 0; aC3[i] = 0; }

    for (int k0 = 0; k0 < NU_; k0 += BK) {
        {
            const int r = tid >> 2, q = tid & 3;
            float4 v = *(const float4*)&u[(size_t)(m0 + r) * NU_ + k0 + q * 4];
            As[r][q * 4 + 0] = v.x; As[r][q * 4 + 1] = v.y;
            As[r][q * 4 + 2] = v.z; As[r][q * 4 + 3] = v.w;
        }
        {
            const int k2 = tid >> 5, cg = tid & 31;
            const float2 w0 = *(const float2*)&W[(size_t)(k0 + 2 * k2) * NX_ + n0 + cg * 2];
            const float2 w1 = *(const float2*)&W[(size_t)(k0 + 2 * k2 + 1) * NX_ + n0 + cg * 2];
            Bs2[k2][cg * 2 + 0] = pack2(w0.x, w1.x);
            Bs2[k2][cg * 2 + 1] = pack2(w0.y, w1.y);
        }
        __syncthreads();
#pragma unroll
        for (int k2 = 0; k2 < BK / 2; ++k2) {
            const ulonglong2* bp = (const ulonglong2*)&Bs2[k2][tx * 4];
            const ulonglong2 b01 = bp[0];
            const ulonglong2 b23 = bp[1];
#pragma unroll
            for (int i = 0; i < 4; i++) {
                const u64 a = *(const u64*)&As[ty * 4 + i][k2 * 2];
                ffma2(aC0[i], a, b01.x);
                ffma2(aC1[i], a, b01.y);
                ffma2(aC2[i], a, b23.x);
                ffma2(aC3[i], a, b23.y);
            }
        }
        __syncthreads();
    }

    const float b0 = __ldg(&bias[n0 + tx * 4 + 0]);
    const float b1 = __ldg(&bias[n0 + tx * 4 + 1]);
    const float b2 = __ldg(&bias[n0 + tx * 4 + 2]);
    const float b3 = __ldg(&bias[n0 + tx * 4 + 3]);
#pragma unroll
    for (int i = 0; i < 4; i++) {
        float4 o = make_float4(hadd2(aC0[i]) + b0, hadd2(aC1[i]) + b1,
                               hadd2(aC2[i]) + b2, hadd2(aC3[i]) + b3);
        *(float4*)&out[(size_t)(m0 + ty * 4 + i) * NX_ + n0 + tx * 4] = o;
    }
}

// ---------------- Phase 2: persistent recurrence (warp-private pipelines) ----------------
// Smem U layouts (k-pair interleaved):
//  Uzp: [k2][col][4] = {Uz[2k2,c], Uz[2k2+1,c], Uf[2k2,c], Uf[2k2+1,c]}  (16384 f)
//  Urp: [k2][col][2] = {Ur[2k2,c], Ur[2k2+1,c]}                          (8192 f)
extern __shared__ float recur_smem[];

__global__ void __launch_bounds__(RTHREADS, 1) recur_kernel(
    const float* __restrict__ Uz, const float* __restrict__ Uf, const float* __restrict__ Ur,
    float* __restrict__ out)
{
    float* Uzp  = recur_smem;                    // 16384 f
    float* Urp  = Uzp + NX_ * 16;                // 8192 f
    float* bufs = Urp + NX_ * 8;                 // 8 warps * 3264 f
    u64*   scr  = (u64*)(bufs + 8 * WREGION);    // 128 slots * 8 u64 = 8KB

    const int tid  = threadIdx.x;
    const int bid  = blockIdx.x;
    const int j0   = bid * CPB;
    const int warp = tid >> 5;
    const int lane = tid & 31;

    const int s     = tid & 127;
    const int khalf = tid >> 7;                // 0: even chunks, 1: odd chunks
    const int row   = s >> 1;
    const int ui    = s & 1;
    const int jb    = j0 + ui * 4;

    float* wbuf   = bufs + warp * WREGION;     // warp-private ring
    const int r0  = 16 * (warp & 3);           // warp's row base
    const int rl  = row & 15;                  // row within warp region

    // Stage U slices, k-pair interleaved (one-time)
    for (int i = tid; i < (NX_ / 2) * CPB; i += RTHREADS) {
        const int k2 = i >> 3, col = i & 7;
        const float* pz = &Uz[(size_t)(2 * k2) * NX_ + j0 + col];
        const float* pf = &Uf[(size_t)(2 * k2) * NX_ + j0 + col];
        const float* pr = &Ur[(size_t)(2 * k2) * NX_ + j0 + col];
        float* uz = &Uzp[k2 * 32 + col * 4];
        uz[0] = pz[0]; uz[1] = pz[NX_];
        uz[2] = pf[0]; uz[3] = pf[NX_];
        float* ur = &Urp[k2 * 16 + col * 2];
        ur[0] = pr[0]; ur[1] = pr[NX_];
    }
    __syncthreads();

    const ulonglong2* UzT = (const ulonglong2*)Uzp + ui * 4;
    const ulonglong2* UrT = (const ulonglong2*)Urp + ui * 2;

    float* xcur  = d_xA;
    float* xnext = d_xB;
    unsigned target = GBLKS;

    float zv[4];     // z gate values (khalf==0 threads)
    float4 xc;       // this thread's own 4 state cols, carried in registers
    if (khalf == 0) xc = *(const float4*)&d_xA[(size_t)row * NX_ + jb];

    for (int t = 0; t < T_; ++t) {
        // ================= ZF phase: z = sig(az + x@Uz), f = sig(af + x@Uf) ============
        u64 az0 = 0, az1 = 0, az2 = 0, az3 = 0;
        u64 af0 = 0, af1 = 0, af2 = 0, af3 = 0;
        float4 az4, af4;
        if (khalf == 0) {
            const size_t aoff = ((size_t)row * T_ + t) * NX_ + jb;
            az4 = __ldcs((const float4*)&d_az[aoff]);
            af4 = __ldcs((const float4*)&d_af[aoff]);
            // io_delay: output at step t is the PRE-update state (in registers)
            __stcs((float4*)&out[aoff], xc);
        }

        // warp-private pipeline over this khalf's 8 chunks (c = 2p + khalf)
        load_chunk_w(wbuf, xcur, r0, 0, khalf, lane);
        load_chunk_w(wbuf, xcur, r0, 1, 2 + khalf, lane);
#pragma unroll 1
        for (int p = 0; p < 8; ++p) {
            if (p < 7) cp_wait<1>(); else cp_wait<0>();
            __syncwarp();
            const u64* xb = (const u64*)(wbuf + (p % 3) * WBUFF + rl * XLD);
            const int k2b = (2 * p + khalf) * (KC / 2);
#pragma unroll 8
            for (int kk2 = 0; kk2 < KC / 2; ++kk2) {
                const u64 xp = xb[kk2];
                const ulonglong2* Up = UzT + (size_t)(k2b + kk2) * 8;
                const ulonglong2 U0 = Up[0], U1 = Up[1];
                ffma2(az0, xp, U0.x); ffma2(af0, xp, U0.y);
                ffma2(az1, xp, U1.x); ffma2(af1, xp, U1.y);
                const ulonglong2 U2 = Up[2], U3 = Up[3];
                ffma2(az2, xp, U2.x); ffma2(af2, xp, U2.y);
                ffma2(az3, xp, U3.x); ffma2(af3, xp, U3.y);
            }
            __syncwarp();   // all lanes done reading slot p%3 before it is refilled
            if (p < 6) load_chunk_w(wbuf, xcur, r0, (p + 2) % 3, 2 * (p + 2) + khalf, lane);
        }
        // cross-half reduction
        if (khalf == 1) {
            ulonglong2* dst = (ulonglong2*)(scr + (size_t)s * 8);
            dst[0] = make_ulonglong2(az0, az1);
            dst[1] = make_ulonglong2(az2, az3);
            dst[2] = make_ulonglong2(af0, af1);
            dst[3] = make_ulonglong2(af2, af3);
        }
        __syncthreads();
        if (khalf == 0) {
            const ulonglong2* sp = (const ulonglong2*)(scr + (size_t)s * 8);
            const ulonglong2 oa = sp[0], ob = sp[1], oc = sp[2], od = sp[3];
            az0 = fadd2(az0, oa.x); az1 = fadd2(az1, oa.y);
            az2 = fadd2(az2, ob.x); az3 = fadd2(az3, ob.y);
            af0 = fadd2(af0, oc.x); af1 = fadd2(af1, oc.y);
            af2 = fadd2(af2, od.x); af3 = fadd2(af3, od.y);

            const float zp0 = hadd2(az0) + az4.x, zp1 = hadd2(az1) + az4.y;
            const float zp2 = hadd2(az2) + az4.z, zp3 = hadd2(az3) + az4.w;
            const float fp0 = hadd2(af0) + af4.x, fp1 = hadd2(af1) + af4.y;
            const float fp2 = hadd2(af2) + af4.z, fp3 = hadd2(af3) + af4.w;

            zv[0] = 1.0f / (1.0f + __expf(-zp0));
            zv[1] = 1.0f / (1.0f + __expf(-zp1));
            zv[2] = 1.0f / (1.0f + __expf(-zp2));
            zv[3] = 1.0f / (1.0f + __expf(-zp3));
            float4 g4;
            g4.x = xc.x / (1.0f + __expf(-fp0));
            g4.y = xc.y / (1.0f + __expf(-fp1));
            g4.z = xc.z / (1.0f + __expf(-fp2));
            g4.w = xc.w / (1.0f + __expf(-fp3));
            __stcg((float4*)&d_g[(size_t)row * NX_ + jb], g4);
        }
        grid_barrier(target); target += GBLKS;

        // ================= R phase: r = tanh(ar + g@Ur); x_next = z*x + (1-z)*r ========
        u64 ar0 = 0, ar1 = 0, ar2 = 0, ar3 = 0;
        float4 ar4;
        if (khalf == 0)
            ar4 = __ldcs((const float4*)&d_ar[((size_t)row * T_ + t) * NX_ + jb]);

        load_chunk_w(wbuf, d_g, r0, 0, khalf, lane);
        load_chunk_w(wbuf, d_g, r0, 1, 2 + khalf, lane);
#pragma unroll 1
        for (int p = 0; p < 8; ++p) {
            if (p < 7) cp_wait<1>(); else cp_wait<0>();
            __syncwarp();
            const u64* gb = (const u64*)(wbuf + (p % 3) * WBUFF + rl * XLD);
            const int k2b = (2 * p + khalf) * (KC / 2);
#pragma unroll 8
            for (int kk2 = 0; kk2 < KC / 2; ++kk2) {
                const u64 gp = gb[kk2];
                const ulonglong2* Up = UrT + (size_t)(k2b + kk2) * 4;
                const ulonglong2 V0 = Up[0];
                ffma2(ar0, gp, V0.x); ffma2(ar1, gp, V0.y);
                const ulonglong2 V1 = Up[1];
                ffma2(ar2, gp, V1.x); ffma2(ar3, gp, V1.y);
            }
            __syncwarp();
            if (p < 6) load_chunk_w(wbuf, d_g, r0, (p + 2) % 3, 2 * (p + 2) + khalf, lane);
        }
        if (khalf == 1) {
            ulonglong2* dst = (ulonglong2*)(scr + (size_t)s * 8);
            dst[0] = make_ulonglong2(ar0, ar1);
            dst[1] = make_ulonglong2(ar2, ar3);
        }
        __syncthreads();
        if (khalf == 0) {
            const ulonglong2* sp = (const ulonglong2*)(scr + (size_t)s * 8);
            const ulonglong2 oa = sp[0], ob = sp[1];
            ar0 = fadd2(ar0, oa.x); ar1 = fadd2(ar1, oa.y);
            ar2 = fadd2(ar2, ob.x); ar3 = fadd2(ar3, ob.y);

            const float rp0 = hadd2(ar0) + ar4.x, rp1 = hadd2(ar1) + ar4.y;
            const float rp2 = hadd2(ar2) + ar4.z, rp3 = hadd2(ar3) + ar4.w;
            float4 xn;
            xn.x = zv[0] * xc.x + (1.0f - zv[0]) * tanhf(rp0);
            xn.y = zv[1] * xc.y + (1.0f - zv[1]) * tanhf(rp1);
            xn.z = zv[2] * xc.z + (1.0f - zv[2]) * tanhf(rp2);
            xn.w = zv[3] * xc.w + (1.0f - zv[3]) * tanhf(rp3);
            __stcg((float4*)&xnext[(size_t)row * NX_ + jb], xn);
            xc = xn;   // carry own state in registers
        }
        grid_barrier(target); target += GBLKS;

        float* tmp = xcur; xcur = xnext; xnext = tmp;
    }
}

// ---------------- launch ----------------
extern "C" void kernel_launch(void* const* d_in, const int* in_sizes, int n_in,
                              void* d_out, int out_size) {
    const float* u  = (const float*)d_in[0];
    const float* x0 = (const float*)d_in[1];
    const float* Wz = (const float*)d_in[2];
    const float* Uz = (const float*)d_in[3];
    const float* bz = (const float*)d_in[4];
    const float* Wf = (const float*)d_in[5];
    const float* Uf = (const float*)d_in[6];
    const float* bf = (const float*)d_in[7];
    const float* Wr = (const float*)d_in[8];
    const float* Ur = (const float*)d_in[9];
    const float* br = (const float*)d_in[10];
    float* out = (float*)d_out;

    init_kernel<<<64, 256>>>(x0);

    dim3 g1(NX_ / BN, (B_ * T_) / BM, 3);
    inproj_kernel<<<g1, 256>>>(u, Wz, Wf, Wr, bz, bf, br);

    // smem: Uzp 16384 + Urp 8192 + warp bufs 8*3264 + scr 2048 floats = 210,944 B
    const int smem_bytes = (NX_ * 16 + NX_ * 8 + 8 * WREGION + 2048) * (int)sizeof(float);
    cudaFuncSetAttribute(recur_kernel, cudaFuncAttributeMaxDynamicSharedMemorySize, smem_bytes);
    recur_kernel<<<GBLKS, RTHREADS, smem_bytes>>>(Uz, Uf, Ur, out);
}